// round 1
// baseline (speedup 1.0000x reference)
#include <cuda_runtime.h>
#include <cuda_bf16.h>

// Problem sizes (fixed by the reference: B=4, L=512, D=256)
#define B 4
#define L 512
#define D 256
#define R_SIZE (B*L*D)        // 524288 floats (r)
#define A_SIZE (B*L*L)        // 1048576 floats (alpha)

#define TILE 64               // i/j tile for scores kernel
#define NT   (L/TILE)         // 8 tiles per dim
#define NPAIR (NT*(NT+1)/2)   // 36 upper-tri tile pairs per batch
#define SH_STRIDE 257         // padded row stride (bank-conflict free)

// 4 MB scratch for the pre-softmax scores
__device__ float g_scores[B*L*L];

__device__ __forceinline__ float tanh_approx(float x) {
    float y;
    asm("tanh.approx.f32 %0, %1;" : "=f"(y) : "f"(x));
    return y;
}

// ---------------------------------------------------------------------------
// Kernel 1: scores[b,i,j] = sum_d tanh(H[b,i,d]+H[b,j,d])*w[d] + bias
// Symmetric => compute upper-triangle 64x64 tiles only, mirror on write.
// Grid: B*NPAIR = 144 blocks, 256 threads. Each thread: 4x4 micro-tile.
// ---------------------------------------------------------------------------
__global__ void scores_kernel(const float* __restrict__ H,
                              const float* __restrict__ w,
                              const float* __restrict__ bias_p) {
    extern __shared__ float sm[];
    float* sHi = sm;                       // TILE * SH_STRIDE
    float* sHj = sm + TILE * SH_STRIDE;    // TILE * SH_STRIDE
    float* sW  = sm + 2 * TILE * SH_STRIDE; // D

    const int blk = blockIdx.x;
    const int b   = blk / NPAIR;
    int p = blk % NPAIR;
    int ti = 0, rowlen = NT;
    while (p >= rowlen) { p -= rowlen; ++ti; --rowlen; }
    const int tj = ti + p;
    const int i0 = ti * TILE;
    const int j0 = tj * TILE;

    const int tid = threadIdx.x;
    const float* Hb = H + (size_t)b * L * D;

    if (tid < D) sW[tid] = w[tid];

    // Load Hi tile (TILE x D) and Hj tile via float4 global loads, scalar STS
    // (padding 257 prevents float4 smem alignment; STS cost is negligible).
    const int F4_PER_TILE = TILE * D / 4;   // 4096
    #pragma unroll
    for (int it = 0; it < F4_PER_TILE / 256; ++it) {
        int e = tid + 256 * it;
        int row = e >> 6;          // D/4 = 64 float4 per row
        int c4  = e & 63;
        float4 v = *reinterpret_cast<const float4*>(Hb + (size_t)(i0 + row) * D + 4 * c4);
        float* dst = sHi + row * SH_STRIDE + 4 * c4;
        dst[0] = v.x; dst[1] = v.y; dst[2] = v.z; dst[3] = v.w;
    }
    #pragma unroll
    for (int it = 0; it < F4_PER_TILE / 256; ++it) {
        int e = tid + 256 * it;
        int row = e >> 6;
        int c4  = e & 63;
        float4 v = *reinterpret_cast<const float4*>(Hb + (size_t)(j0 + row) * D + 4 * c4);
        float* dst = sHj + row * SH_STRIDE + 4 * c4;
        dst[0] = v.x; dst[1] = v.y; dst[2] = v.z; dst[3] = v.w;
    }
    __syncthreads();

    const int tx = tid & 15;
    const int ty = tid >> 4;

    float acc[4][4];
    #pragma unroll
    for (int m = 0; m < 4; ++m)
        #pragma unroll
        for (int n = 0; n < 4; ++n) acc[m][n] = 0.0f;

    #pragma unroll 2
    for (int d = 0; d < D; ++d) {
        float wd = sW[d];
        float hi[4], hj[4];
        #pragma unroll
        for (int m = 0; m < 4; ++m) hi[m] = sHi[(ty + 16 * m) * SH_STRIDE + d];
        #pragma unroll
        for (int n = 0; n < 4; ++n) hj[n] = sHj[(tx + 16 * n) * SH_STRIDE + d];
        #pragma unroll
        for (int m = 0; m < 4; ++m)
            #pragma unroll
            for (int n = 0; n < 4; ++n)
                acc[m][n] = fmaf(tanh_approx(hi[m] + hj[n]), wd, acc[m][n]);
    }

    const float bias = *bias_p;
    const int mirror = (ti != tj);
    #pragma unroll
    for (int m = 0; m < 4; ++m) {
        int gi = i0 + ty + 16 * m;
        #pragma unroll
        for (int n = 0; n < 4; ++n) {
            int gj = j0 + tx + 16 * n;
            float v = acc[m][n] + bias;
            g_scores[((size_t)b * L + gi) * L + gj] = v;
            if (mirror)
                g_scores[((size_t)b * L + gj) * L + gi] = v;
        }
    }
}

// ---------------------------------------------------------------------------
// Kernel 2: row softmax of g_scores -> alpha (written directly into d_out).
// Grid: B*L = 2048 blocks, 256 threads, 2 elems/thread.
// ---------------------------------------------------------------------------
__global__ void softmax_kernel(float* __restrict__ out_alpha) {
    const int row = blockIdx.x;              // 0 .. B*L-1
    const int tid = threadIdx.x;
    const float* srow = g_scores + (size_t)row * L;

    float v0 = srow[tid];
    float v1 = srow[tid + 256];

    __shared__ float red_max[8];
    __shared__ float red_sum[8];
    const int wid = tid >> 5, lane = tid & 31;

    // block max
    float m = fmaxf(v0, v1);
    #pragma unroll
    for (int o = 16; o; o >>= 1) m = fmaxf(m, __shfl_xor_sync(0xffffffffu, m, o));
    if (lane == 0) red_max[wid] = m;
    __syncthreads();
    float M = red_max[0];
    #pragma unroll
    for (int i = 1; i < 8; ++i) M = fmaxf(M, red_max[i]);

    float e0 = __expf(v0 - M);
    float e1 = __expf(v1 - M);

    float s = e0 + e1;
    #pragma unroll
    for (int o = 16; o; o >>= 1) s += __shfl_xor_sync(0xffffffffu, s, o);
    if (lane == 0) red_sum[wid] = s;
    __syncthreads();
    float S = red_sum[0];
    #pragma unroll
    for (int i = 1; i < 8; ++i) S += red_sum[i];

    float inv = 1.0f / S;
    out_alpha[(size_t)row * L + tid]       = e0 * inv;
    out_alpha[(size_t)row * L + tid + 256] = e1 * inv;
}

// ---------------------------------------------------------------------------
// Kernel 3: r[b] = alpha[b] (LxL) @ H[b] (LxD).  Register-tiled FMA GEMM.
// Grid: (D/64, L/64, B) = (4, 8, 4) = 128 blocks, 256 threads, 4x4 tiles.
// ---------------------------------------------------------------------------
__global__ void gemm_kernel(const float* __restrict__ alpha,
                            const float* __restrict__ H,
                            float* __restrict__ r) {
    const int b  = blockIdx.z;
    const int i0 = blockIdx.y * 64;
    const int d0 = blockIdx.x * 64;

    const float* A  = alpha + (size_t)b * L * L;
    const float* Bm = H     + (size_t)b * L * D;
    float*       C  = r     + (size_t)b * L * D;

    __shared__ float As[32][65];   // [k][i], padded
    __shared__ float Bs[32][64];   // [k][d]

    const int tid = threadIdx.x;
    const int tx = tid & 15, ty = tid >> 4;

    float acc[4][4];
    #pragma unroll
    for (int m = 0; m < 4; ++m)
        #pragma unroll
        for (int n = 0; n < 4; ++n) acc[m][n] = 0.0f;

    for (int k0 = 0; k0 < L; k0 += 32) {
        #pragma unroll
        for (int it = 0; it < 8; ++it) {
            int e = tid + 256 * it;          // 64*32 elems
            int ai = e >> 5, ak = e & 31;
            As[ak][ai] = A[(size_t)(i0 + ai) * L + k0 + ak];
        }
        #pragma unroll
        for (int it = 0; it < 8; ++it) {
            int e = tid + 256 * it;          // 32*64 elems
            int bk = e >> 6, bd = e & 63;
            Bs[bk][bd] = Bm[(size_t)(k0 + bk) * D + d0 + bd];
        }
        __syncthreads();

        #pragma unroll
        for (int kk = 0; kk < 32; ++kk) {
            float a[4], bv[4];
            #pragma unroll
            for (int m = 0; m < 4; ++m) a[m] = As[kk][ty + 16 * m];
            #pragma unroll
            for (int n = 0; n < 4; ++n) bv[n] = Bs[kk][tx + 16 * n];
            #pragma unroll
            for (int m = 0; m < 4; ++m)
                #pragma unroll
                for (int n = 0; n < 4; ++n)
                    acc[m][n] = fmaf(a[m], bv[n], acc[m][n]);
        }
        __syncthreads();
    }

    #pragma unroll
    for (int m = 0; m < 4; ++m) {
        int gi = i0 + ty + 16 * m;
        #pragma unroll
        for (int n = 0; n < 4; ++n)
            C[(size_t)gi * D + d0 + tx + 16 * n] = acc[m][n];
    }
}

// ---------------------------------------------------------------------------
extern "C" void kernel_launch(void* const* d_in, const int* in_sizes, int n_in,
                              void* d_out, int out_size) {
    const float* H    = (const float*)d_in[0];
    const float* w    = (const float*)d_in[1];
    const float* bias = (const float*)d_in[2];

    float* out   = (float*)d_out;
    float* r     = out;            // first R_SIZE floats
    float* alpha = out + R_SIZE;   // next A_SIZE floats

    const int smem_bytes = (2 * TILE * SH_STRIDE + D) * (int)sizeof(float);
    cudaFuncSetAttribute(scores_kernel,
                         cudaFuncAttributeMaxDynamicSharedMemorySize, smem_bytes);

    scores_kernel<<<B * NPAIR, 256, smem_bytes>>>(H, w, bias);
    softmax_kernel<<<B * L, 256>>>(alpha);
    gemm_kernel<<<dim3(D / 64, L / 64, B), 256>>>(alpha, H, r);
}